// round 15
// baseline (speedup 1.0000x reference)
#include <cuda_runtime.h>
#include <cuda_fp16.h>
#include <math.h>
#include <stdint.h>

#define HSZ 1024
#define NH 16
#define DH 64
#define SEQ 2048
#define NB 2
#define MTOT (NB*SEQ)
#define LOG2E 1.4426950408889634f
#define QSCALE (0.125f * LOG2E)

// fp16 GEMM inputs
__device__ __half g_x[(size_t)MTOT * HSZ];
__device__ __half g_w[3 * (size_t)HSZ * HSZ];   // transposed [n][k]
// attention operands, single fp16, [bh][s][d]
__device__ __half g_q[(size_t)MTOT * HSZ];   // pre-scaled by 0.125*log2e
__device__ __half g_k[(size_t)MTOT * HSZ];
__device__ __half g_v[(size_t)MTOT * HSZ];

// ---------------------------------------------------------------------------
// mma / ldmatrix / cp.async helpers
// ---------------------------------------------------------------------------
__device__ __forceinline__ void mma_f16(float d[4], const uint32_t a[4],
                                        const uint32_t b[2]) {
    asm volatile(
        "mma.sync.aligned.m16n8k16.row.col.f32.f16.f16.f32 "
        "{%0,%1,%2,%3}, {%4,%5,%6,%7}, {%8,%9}, {%0,%1,%2,%3};\n"
        : "+f"(d[0]), "+f"(d[1]), "+f"(d[2]), "+f"(d[3])
        : "r"(a[0]), "r"(a[1]), "r"(a[2]), "r"(a[3]), "r"(b[0]), "r"(b[1]));
}
__device__ __forceinline__ uint32_t cvta_sm(const void* p) {
    uint32_t a;
    asm("{ .reg .u64 t; cvta.to.shared.u64 t, %1; cvt.u32.u64 %0, t; }"
        : "=r"(a) : "l"(p));
    return a;
}
__device__ __forceinline__ void ldsm_x4(uint32_t r[4], uint32_t addr) {
    asm volatile("ldmatrix.sync.aligned.m8n8.x4.shared.b16 {%0,%1,%2,%3}, [%4];"
                 : "=r"(r[0]), "=r"(r[1]), "=r"(r[2]), "=r"(r[3]) : "r"(addr));
}
__device__ __forceinline__ void ldsm_x4_t(uint32_t r[4], uint32_t addr) {
    asm volatile("ldmatrix.sync.aligned.m8n8.x4.trans.shared.b16 {%0,%1,%2,%3}, [%4];"
                 : "=r"(r[0]), "=r"(r[1]), "=r"(r[2]), "=r"(r[3]) : "r"(addr));
}
__device__ __forceinline__ void cp16(uint32_t dst, const void* src) {
    asm volatile("cp.async.cg.shared.global [%0], [%1], 16;"
                 :: "r"(dst), "l"(src) : "memory");
}
#define CP_COMMIT() asm volatile("cp.async.commit_group;" ::: "memory")
#define CP_WAIT(n)  asm volatile("cp.async.wait_group %0;" :: "n"(n) : "memory")

__device__ __forceinline__ uint32_t addrA(uint32_t base, int r0, int k0,
                                          int stride, int lane) {
    int row = r0 + (lane & 7) + ((lane >> 3) & 1) * 8;
    int col = k0 + (lane >> 4) * 8;
    return base + (uint32_t)(row * stride + col) * 2;
}
__device__ __forceinline__ uint32_t addrB(uint32_t base, int n0, int k0,
                                          int stride, int lane) {
    int row = n0 + (lane & 7) + (lane >> 4) * 8;
    int col = k0 + ((lane >> 3) & 1) * 8;
    return base + (uint32_t)(row * stride + col) * 2;
}
__device__ __forceinline__ uint32_t addrVT(uint32_t base, int d0, int s0,
                                           int stride, int lane) {
    int row = s0 + (lane & 7) + ((lane >> 3) & 1) * 8;
    int col = d0 + (lane >> 4) * 8;
    return base + (uint32_t)(row * stride + col) * 2;
}
__device__ __forceinline__ void ldA_g16(uint32_t a[4], const __half* base,
                                        int k0, int stride, int lane) {
    const __half* p = base + (size_t)(lane >> 2) * stride + k0 + ((lane & 3) << 1);
    a[0] = *(const uint32_t*)p;
    a[1] = *(const uint32_t*)(p + 8 * stride);
    a[2] = *(const uint32_t*)(p + 8);
    a[3] = *(const uint32_t*)(p + 8 * stride + 8);
}
__device__ __forceinline__ float ex2f(float x) {
    float y;
    asm("ex2.approx.ftz.f32 %0, %1;" : "=f"(y) : "f"(x));
    return y;
}
__device__ __forceinline__ uint32_t packhf(float lo, float hi) {
    uint32_t r;
    asm("cvt.rn.f16x2.f32 %0, %1, %2;" : "=r"(r) : "f"(hi), "f"(lo));
    return r;
}

// ---------------------------------------------------------------------------
// Convert hidden_states to fp16
// ---------------------------------------------------------------------------
__global__ __launch_bounds__(256) void conv_x_kernel(const float* __restrict__ X)
{
    size_t i = ((size_t)blockIdx.x * 256 + threadIdx.x) * 4;
    float4 v = *(const float4*)(X + i);
    uint32_t p0 = packhf(v.x, v.y);
    uint32_t p1 = packhf(v.z, v.w);
    *(uint32_t*)(g_x + i)     = p0;
    *(uint32_t*)(g_x + i + 2) = p1;
}

// ---------------------------------------------------------------------------
// Transpose + convert weights: Wt[n][k] = W[k][n], fp16
// ---------------------------------------------------------------------------
__global__ __launch_bounds__(256) void conv_w_kernel(
    const float* __restrict__ Wq, const float* __restrict__ Wk,
    const float* __restrict__ Wv)
{
    __shared__ float t[32][33];
    const int z = blockIdx.z;
    const float* W = (z == 0) ? Wq : (z == 1) ? Wk : Wv;
    __half* T = g_w + (size_t)z * HSZ * HSZ;

    const int n0 = blockIdx.x * 32;
    const int k0 = blockIdx.y * 32;
    const int tx = threadIdx.x & 31;
    const int ty = threadIdx.x >> 5;

#pragma unroll
    for (int j = 0; j < 4; j++) {
        int k = k0 + ty + j * 8;
        t[ty + j * 8][tx] = W[(size_t)k * HSZ + n0 + tx];
    }
    __syncthreads();
#pragma unroll
    for (int j = 0; j < 4; j++) {
        int r = ty + j * 8;
        T[(size_t)(n0 + r) * HSZ + k0 + tx] = __float2half(t[tx][r]);
    }
}

// ---------------------------------------------------------------------------
// QKV GEMM, single-term fp16 HMMA, ldmatrix + cp.async double buffer.
// CTA 128x128, BK=64, 8 warps, 2 CTAs/SM.
// Dynamic smem: 2 stages x 2 arrays x 18432 B = 73728 B.
// ---------------------------------------------------------------------------
extern __shared__ __align__(16) char dsm[];

#define QARR_B   18432u
#define QSTAGE_B 36864u

__global__ __launch_bounds__(256, 2) void qkv_mma_kernel(
    const float* __restrict__ bq, const float* __restrict__ bk,
    const float* __restrict__ bv)
{
    const int tid  = threadIdx.x;
    const int lane = tid & 31;
    const int wid  = tid >> 5;
    const int wr   = wid >> 1;
    const int wc   = wid & 1;

    const int n0  = blockIdx.x * 128;
    const int m0  = blockIdx.y * 128;
    const int mat = blockIdx.z;

    const __half* Wt = g_w + (size_t)mat * HSZ * HSZ;
    const float* bias = (mat == 0) ? bq : (mat == 1) ? bk : bv;

    const uint32_t smBase = cvta_sm(dsm);

    const int lrow = tid >> 1;            // 0..127
    const int lcb  = (tid & 1) * 32;      // halves

    auto load_chunk = [&](int st, int gk) {
        size_t ga = (size_t)(m0 + lrow) * HSZ + gk + lcb;
        size_t gb = (size_t)(n0 + lrow) * HSZ + gk + lcb;
        uint32_t so = smBase + st * QSTAGE_B + (uint32_t)(lrow * 72 + lcb) * 2;
#pragma unroll
        for (int u = 0; u < 4; u++) {
            cp16(so + u * 16,          g_x + ga + u * 8);
            cp16(so + QARR_B + u * 16, Wt + gb + u * 8);
        }
    };

    float acc[2][8][4];
#pragma unroll
    for (int i = 0; i < 2; i++)
#pragma unroll
        for (int j = 0; j < 8; j++)
#pragma unroll
            for (int u = 0; u < 4; u++) acc[i][j][u] = 0.0f;

    load_chunk(0, 0);
    CP_COMMIT();
    load_chunk(1, 64);
    CP_COMMIT();

    const int NCH = HSZ / 64;   // 16
    for (int kc = 0; kc < NCH; kc++) {
        const int st = kc & 1;
        if (kc + 1 < NCH) { CP_WAIT(1); } else { CP_WAIT(0); }
        __syncthreads();

        const uint32_t bA = smBase + st * QSTAGE_B;
        const uint32_t bB = bA + QARR_B;

#pragma unroll
        for (int ks = 0; ks < 4; ks++) {
            uint32_t a0[4], a1[4];
            ldsm_x4(a0, addrA(bA, wr * 32,      ks * 16, 72, lane));
            ldsm_x4(a1, addrA(bA, wr * 32 + 16, ks * 16, 72, lane));
#pragma unroll
            for (int np = 0; np < 4; np++) {
                uint32_t bb[4];
                ldsm_x4(bb, addrB(bB, wc * 64 + np * 16, ks * 16, 72, lane));
                mma_f16(acc[0][2 * np],     a0, bb);
                mma_f16(acc[0][2 * np + 1], a0, bb + 2);
                mma_f16(acc[1][2 * np],     a1, bb);
                mma_f16(acc[1][2 * np + 1], a1, bb + 2);
            }
        }

        __syncthreads();
        if (kc + 2 < NCH) {
            load_chunk(st, (kc + 2) * 64);
            CP_COMMIT();
        }
    }

    // epilogue: bias, (Q prescale), pack fp16, store [bh][s][d]
    __half* dst = (mat == 0) ? g_q : (mat == 1) ? g_k : g_v;
#pragma unroll
    for (int mt = 0; mt < 2; mt++) {
#pragma unroll
        for (int nt = 0; nt < 8; nt++) {
            int mbase = m0 + wr * 32 + mt * 16 + (lane >> 2);
            int c = n0 + wc * 64 + nt * 8 + ((lane & 3) << 1);
            float b0 = bias[c], b1 = bias[c + 1];
            int hh = c >> 6, d = c & 63;
#pragma unroll
            for (int hf = 0; hf < 2; hf++) {
                int mm = mbase + hf * 8;
                float v0 = acc[mt][nt][hf * 2 + 0] + b0;
                float v1 = acc[mt][nt][hf * 2 + 1] + b1;
                if (mat == 0) { v0 *= QSCALE; v1 *= QSCALE; }
                int b_ = mm >> 11, s = mm & (SEQ - 1);
                size_t bh = (size_t)(b_ * NH + hh);
                *(uint32_t*)(dst + (bh * SEQ + s) * DH + d) = packhf(v0, v1);
            }
        }
    }
}

// ---------------------------------------------------------------------------
// Flash attention: single-term fp16 HMMA, fixed softmax max, cp.async
// double-buffered K/V staged 128 keys per barrier window (two 64-key
// sub-tiles between one sync pair). CTA = 128 q-rows (8 warps), 2 CTAs/SM.
// Each staged array: 128 rows x 72 halves = 18432 B.
// Dynamic smem: 2 stages x 2 arrays x 18432 B = 73728 B.
// ---------------------------------------------------------------------------
#define ARR_B   18432u
#define STAGE_B 36864u
#define NKT     (SEQ / 128)

__global__ __launch_bounds__(256, 2) void attn_mma_kernel(
    const float* __restrict__ mask, float* __restrict__ out)
{
    const int tid  = threadIdx.x;
    const int lane = tid & 31;
    const int wid  = tid >> 5;

    const int bh = blockIdx.y;
    const int b  = bh >> 4;
    const int h  = bh & 15;
    const int q0 = blockIdx.x * 128 + wid * 16;

    const float* mrow = mask + (size_t)b * SEQ;
    const uint32_t smBase = cvta_sm(dsm);

    const int lrow = tid >> 1;            // 0..127 (key row)
    const int lcb  = (tid & 1) * 32;      // halves

    // async tile loader: 128 keys of K and V per stage
    auto load_tile = [&](int stage, int k0) {
        size_t ko = ((size_t)bh * SEQ + k0 + lrow) * DH + lcb;
        uint32_t so = smBase + stage * STAGE_B + (uint32_t)(lrow * 72 + lcb) * 2;
#pragma unroll
        for (int u = 0; u < 4; u++) {
            cp16(so + u * 16,          g_k + ko + u * 8);
            cp16(so + ARR_B + u * 16,  g_v + ko + u * 8);
        }
    };

    // Q fragments (fp16, prescaled to log2 domain)
    uint32_t qf[4][4];
    {
        const __half* qb = g_q + ((size_t)bh * SEQ + q0) * DH;
#pragma unroll
        for (int ks = 0; ks < 4; ks++)
            ldA_g16(qf[ks], qb, ks * 16, DH, lane);
    }

    float oacc[8][4];
#pragma unroll
    for (int j = 0; j < 8; j++)
#pragma unroll
        for (int u = 0; u < 4; u++) oacc[j][u] = 0.0f;
    float l1 = 0.0f, l2 = 0.0f;

    load_tile(0, 0);
    CP_COMMIT();
    load_tile(1, 128);
    CP_COMMIT();

    for (int kt = 0; kt < NKT; kt++) {
        const int st = kt & 1;
        if (kt + 1 < NKT) { CP_WAIT(1); } else { CP_WAIT(0); }
        __syncthreads();

        const uint32_t aK = smBase + st * STAGE_B;
        const uint32_t aV = aK + ARR_B;

        // two 64-key sub-tiles inside one barrier window
#pragma unroll
        for (int hf2 = 0; hf2 < 2; hf2++) {
            const int kb = hf2 * 64;           // sub-tile key base (smem rows)
            const int k0 = kt * 128 + kb;      // global key base

            // S = Q K^T
            float sacc[8][4];
#pragma unroll
            for (int j = 0; j < 8; j++)
#pragma unroll
                for (int u = 0; u < 4; u++) sacc[j][u] = 0.0f;
#pragma unroll
            for (int ks = 0; ks < 4; ks++) {
#pragma unroll
                for (int np = 0; np < 4; np++) {
                    uint32_t bb[4];
                    ldsm_x4(bb, addrB(aK, kb + np * 16, ks * 16, 72, lane));
                    mma_f16(sacc[2 * np],     qf[ks], bb);
                    mma_f16(sacc[2 * np + 1], qf[ks], bb + 2);
                }
            }

            // p = 2^(s + mask*log2e)
#pragma unroll
            for (int nt = 0; nt < 8; nt++) {
                float2 mk = *(const float2*)&mrow[k0 + nt * 8 + ((lane & 3) << 1)];
                float a0 = mk.x * LOG2E, a1 = mk.y * LOG2E;
                sacc[nt][0] = ex2f(sacc[nt][0] + a0);
                sacc[nt][1] = ex2f(sacc[nt][1] + a1);
                sacc[nt][2] = ex2f(sacc[nt][2] + a0);
                sacc[nt][3] = ex2f(sacc[nt][3] + a1);
                l1 += sacc[nt][0] + sacc[nt][1];
                l2 += sacc[nt][2] + sacc[nt][3];
            }

            // O += P V (V^T via ldmatrix.trans)
#pragma unroll
            for (int t = 0; t < 4; t++) {
                uint32_t ah[4];
                ah[0] = packhf(sacc[2*t][0],   sacc[2*t][1]);
                ah[1] = packhf(sacc[2*t][2],   sacc[2*t][3]);
                ah[2] = packhf(sacc[2*t+1][0], sacc[2*t+1][1]);
                ah[3] = packhf(sacc[2*t+1][2], sacc[2*t+1][3]);
#pragma unroll
                for (int dp = 0; dp < 4; dp++) {
                    uint32_t bv[4];
                    ldsm_x4_t(bv, addrVT(aV, dp * 16, kb + t * 16, 72, lane));
                    mma_f16(oacc[2 * dp],     ah, bv);
                    mma_f16(oacc[2 * dp + 1], ah, bv + 2);
                }
            }
        }

        __syncthreads();
        if (kt + 2 < NKT) {
            load_tile(st, (kt + 2) * 128);
            CP_COMMIT();
        }
    }

    // final row-sum reduction over the quad
#pragma unroll
    for (int off = 1; off < 4; off <<= 1) {
        l1 += __shfl_xor_sync(0xffffffffu, l1, off);
        l2 += __shfl_xor_sync(0xffffffffu, l2, off);
    }
    float inv1 = 1.0f / l1;
    float inv2 = 1.0f / l2;
    const int s1 = q0 + (lane >> 2);
    const int s2 = s1 + 8;
#pragma unroll
    for (int dt = 0; dt < 8; dt++) {
        int d = dt * 8 + ((lane & 3) << 1);
        float2 o1, o2;
        o1.x = oacc[dt][0] * inv1; o1.y = oacc[dt][1] * inv1;
        o2.x = oacc[dt][2] * inv2; o2.y = oacc[dt][3] * inv2;
        *(float2*)&out[((size_t)b * SEQ + s1) * HSZ + h * DH + d] = o1;
        *(float2*)&out[((size_t)b * SEQ + s2) * HSZ + h * DH + d] = o2;
    }
}

extern "C" void kernel_launch(void* const* d_in, const int* in_sizes, int n_in,
                              void* d_out, int out_size)
{
    const float* hidden = (const float*)d_in[0];
    const float* mask   = (const float*)d_in[1];
    const float* Wq     = (const float*)d_in[2];
    const float* bq     = (const float*)d_in[3];
    const float* Wk     = (const float*)d_in[4];
    const float* bk     = (const float*)d_in[5];
    const float* Wv     = (const float*)d_in[6];
    const float* bv     = (const float*)d_in[7];
    float* out = (float*)d_out;

    conv_x_kernel<<<(MTOT * HSZ) / (256 * 4), 256>>>(hidden);
    conv_w_kernel<<<dim3(HSZ / 32, HSZ / 32, 3), 256>>>(Wq, Wk, Wv);

    const int QKV_SMEM = 73728;
    cudaFuncSetAttribute(qkv_mma_kernel,
                         cudaFuncAttributeMaxDynamicSharedMemorySize, QKV_SMEM);
    qkv_mma_kernel<<<dim3(8, 32, 3), 256, QKV_SMEM>>>(bq, bk, bv);

    const int ATTN_SMEM = 73728;
    cudaFuncSetAttribute(attn_mma_kernel,
                         cudaFuncAttributeMaxDynamicSharedMemorySize, ATTN_SMEM);
    attn_mma_kernel<<<dim3(SEQ / 128, NB * NH), 256, ATTN_SMEM>>>(mask, out);
}

// round 16
// speedup vs baseline: 1.1028x; 1.1028x over previous
#include <cuda_runtime.h>
#include <cuda_fp16.h>
#include <math.h>
#include <stdint.h>

#define HSZ 1024
#define NH 16
#define DH 64
#define SEQ 2048
#define NB 2
#define MTOT (NB*SEQ)
#define LOG2E 1.4426950408889634f
#define QSCALE (0.125f * LOG2E)

// fp16 GEMM inputs
__device__ __half g_x[(size_t)MTOT * HSZ];
__device__ __half g_w[3 * (size_t)HSZ * HSZ];   // transposed [n][k]
// attention operands, single fp16, [bh][s][d]
__device__ __half g_q[(size_t)MTOT * HSZ];   // pre-scaled by 0.125*log2e
__device__ __half g_k[(size_t)MTOT * HSZ];
__device__ __half g_v[(size_t)MTOT * HSZ];

// ---------------------------------------------------------------------------
// mma / ldmatrix / cp.async helpers
// ---------------------------------------------------------------------------
__device__ __forceinline__ void mma_f16(float d[4], const uint32_t a[4],
                                        const uint32_t b[2]) {
    asm volatile(
        "mma.sync.aligned.m16n8k16.row.col.f32.f16.f16.f32 "
        "{%0,%1,%2,%3}, {%4,%5,%6,%7}, {%8,%9}, {%0,%1,%2,%3};\n"
        : "+f"(d[0]), "+f"(d[1]), "+f"(d[2]), "+f"(d[3])
        : "r"(a[0]), "r"(a[1]), "r"(a[2]), "r"(a[3]), "r"(b[0]), "r"(b[1]));
}
__device__ __forceinline__ uint32_t cvta_sm(const void* p) {
    uint32_t a;
    asm("{ .reg .u64 t; cvta.to.shared.u64 t, %1; cvt.u32.u64 %0, t; }"
        : "=r"(a) : "l"(p));
    return a;
}
__device__ __forceinline__ void ldsm_x4(uint32_t r[4], uint32_t addr) {
    asm volatile("ldmatrix.sync.aligned.m8n8.x4.shared.b16 {%0,%1,%2,%3}, [%4];"
                 : "=r"(r[0]), "=r"(r[1]), "=r"(r[2]), "=r"(r[3]) : "r"(addr));
}
__device__ __forceinline__ void ldsm_x4_t(uint32_t r[4], uint32_t addr) {
    asm volatile("ldmatrix.sync.aligned.m8n8.x4.trans.shared.b16 {%0,%1,%2,%3}, [%4];"
                 : "=r"(r[0]), "=r"(r[1]), "=r"(r[2]), "=r"(r[3]) : "r"(addr));
}
__device__ __forceinline__ void cp16(uint32_t dst, const void* src) {
    asm volatile("cp.async.cg.shared.global [%0], [%1], 16;"
                 :: "r"(dst), "l"(src) : "memory");
}
#define CP_COMMIT() asm volatile("cp.async.commit_group;" ::: "memory")
#define CP_WAIT(n)  asm volatile("cp.async.wait_group %0;" :: "n"(n) : "memory")

__device__ __forceinline__ uint32_t addrA(uint32_t base, int r0, int k0,
                                          int stride, int lane) {
    int row = r0 + (lane & 7) + ((lane >> 3) & 1) * 8;
    int col = k0 + (lane >> 4) * 8;
    return base + (uint32_t)(row * stride + col) * 2;
}
__device__ __forceinline__ uint32_t addrB(uint32_t base, int n0, int k0,
                                          int stride, int lane) {
    int row = n0 + (lane & 7) + (lane >> 4) * 8;
    int col = k0 + ((lane >> 3) & 1) * 8;
    return base + (uint32_t)(row * stride + col) * 2;
}
__device__ __forceinline__ uint32_t addrVT(uint32_t base, int d0, int s0,
                                           int stride, int lane) {
    int row = s0 + (lane & 7) + ((lane >> 3) & 1) * 8;
    int col = d0 + (lane >> 4) * 8;
    return base + (uint32_t)(row * stride + col) * 2;
}
__device__ __forceinline__ void ldA_g16(uint32_t a[4], const __half* base,
                                        int k0, int stride, int lane) {
    const __half* p = base + (size_t)(lane >> 2) * stride + k0 + ((lane & 3) << 1);
    a[0] = *(const uint32_t*)p;
    a[1] = *(const uint32_t*)(p + 8 * stride);
    a[2] = *(const uint32_t*)(p + 8);
    a[3] = *(const uint32_t*)(p + 8 * stride + 8);
}
__device__ __forceinline__ float ex2f(float x) {
    float y;
    asm("ex2.approx.ftz.f32 %0, %1;" : "=f"(y) : "f"(x));
    return y;
}
__device__ __forceinline__ uint32_t packhf(float lo, float hi) {
    uint32_t r;
    asm("cvt.rn.f16x2.f32 %0, %1, %2;" : "=r"(r) : "f"(hi), "f"(lo));
    return r;
}

// ---------------------------------------------------------------------------
// Convert hidden_states to fp16
// ---------------------------------------------------------------------------
__global__ __launch_bounds__(256) void conv_x_kernel(const float* __restrict__ X)
{
    size_t i = ((size_t)blockIdx.x * 256 + threadIdx.x) * 4;
    float4 v = *(const float4*)(X + i);
    uint32_t p0 = packhf(v.x, v.y);
    uint32_t p1 = packhf(v.z, v.w);
    *(uint32_t*)(g_x + i)     = p0;
    *(uint32_t*)(g_x + i + 2) = p1;
}

// ---------------------------------------------------------------------------
// Transpose + convert weights: Wt[n][k] = W[k][n], fp16
// ---------------------------------------------------------------------------
__global__ __launch_bounds__(256) void conv_w_kernel(
    const float* __restrict__ Wq, const float* __restrict__ Wk,
    const float* __restrict__ Wv)
{
    __shared__ float t[32][33];
    const int z = blockIdx.z;
    const float* W = (z == 0) ? Wq : (z == 1) ? Wk : Wv;
    __half* T = g_w + (size_t)z * HSZ * HSZ;

    const int n0 = blockIdx.x * 32;
    const int k0 = blockIdx.y * 32;
    const int tx = threadIdx.x & 31;
    const int ty = threadIdx.x >> 5;

#pragma unroll
    for (int j = 0; j < 4; j++) {
        int k = k0 + ty + j * 8;
        t[ty + j * 8][tx] = W[(size_t)k * HSZ + n0 + tx];
    }
    __syncthreads();
#pragma unroll
    for (int j = 0; j < 4; j++) {
        int r = ty + j * 8;
        T[(size_t)(n0 + r) * HSZ + k0 + tx] = __float2half(t[tx][r]);
    }
}

// ---------------------------------------------------------------------------
// QKV GEMM, single-term fp16 HMMA, ldmatrix + cp.async double buffer.
// CTA 128x128, BK=64, 8 warps, 2 CTAs/SM.
// Dynamic smem: 2 stages x 2 arrays x 18432 B = 73728 B.
// ---------------------------------------------------------------------------
extern __shared__ __align__(16) char dsm[];

#define QARR_B   18432u
#define QSTAGE_B 36864u

__global__ __launch_bounds__(256, 2) void qkv_mma_kernel(
    const float* __restrict__ bq, const float* __restrict__ bk,
    const float* __restrict__ bv)
{
    const int tid  = threadIdx.x;
    const int lane = tid & 31;
    const int wid  = tid >> 5;
    const int wr   = wid >> 1;
    const int wc   = wid & 1;

    const int n0  = blockIdx.x * 128;
    const int m0  = blockIdx.y * 128;
    const int mat = blockIdx.z;

    const __half* Wt = g_w + (size_t)mat * HSZ * HSZ;
    const float* bias = (mat == 0) ? bq : (mat == 1) ? bk : bv;

    const uint32_t smBase = cvta_sm(dsm);

    const int lrow = tid >> 1;            // 0..127
    const int lcb  = (tid & 1) * 32;      // halves

    auto load_chunk = [&](int st, int gk) {
        size_t ga = (size_t)(m0 + lrow) * HSZ + gk + lcb;
        size_t gb = (size_t)(n0 + lrow) * HSZ + gk + lcb;
        uint32_t so = smBase + st * QSTAGE_B + (uint32_t)(lrow * 72 + lcb) * 2;
#pragma unroll
        for (int u = 0; u < 4; u++) {
            cp16(so + u * 16,          g_x + ga + u * 8);
            cp16(so + QARR_B + u * 16, Wt + gb + u * 8);
        }
    };

    float acc[2][8][4];
#pragma unroll
    for (int i = 0; i < 2; i++)
#pragma unroll
        for (int j = 0; j < 8; j++)
#pragma unroll
            for (int u = 0; u < 4; u++) acc[i][j][u] = 0.0f;

    load_chunk(0, 0);
    CP_COMMIT();
    load_chunk(1, 64);
    CP_COMMIT();

    const int NCH = HSZ / 64;   // 16
    for (int kc = 0; kc < NCH; kc++) {
        const int st = kc & 1;
        if (kc + 1 < NCH) { CP_WAIT(1); } else { CP_WAIT(0); }
        __syncthreads();

        const uint32_t bA = smBase + st * QSTAGE_B;
        const uint32_t bB = bA + QARR_B;

#pragma unroll
        for (int ks = 0; ks < 4; ks++) {
            uint32_t a0[4], a1[4];
            ldsm_x4(a0, addrA(bA, wr * 32,      ks * 16, 72, lane));
            ldsm_x4(a1, addrA(bA, wr * 32 + 16, ks * 16, 72, lane));
#pragma unroll
            for (int np = 0; np < 4; np++) {
                uint32_t bb[4];
                ldsm_x4(bb, addrB(bB, wc * 64 + np * 16, ks * 16, 72, lane));
                mma_f16(acc[0][2 * np],     a0, bb);
                mma_f16(acc[0][2 * np + 1], a0, bb + 2);
                mma_f16(acc[1][2 * np],     a1, bb);
                mma_f16(acc[1][2 * np + 1], a1, bb + 2);
            }
        }

        __syncthreads();
        if (kc + 2 < NCH) {
            load_chunk(st, (kc + 2) * 64);
            CP_COMMIT();
        }
    }

    // epilogue: bias, (Q prescale), pack fp16, store [bh][s][d]
    __half* dst = (mat == 0) ? g_q : (mat == 1) ? g_k : g_v;
#pragma unroll
    for (int mt = 0; mt < 2; mt++) {
#pragma unroll
        for (int nt = 0; nt < 8; nt++) {
            int mbase = m0 + wr * 32 + mt * 16 + (lane >> 2);
            int c = n0 + wc * 64 + nt * 8 + ((lane & 3) << 1);
            float b0 = bias[c], b1 = bias[c + 1];
            int hh = c >> 6, d = c & 63;
#pragma unroll
            for (int hf = 0; hf < 2; hf++) {
                int mm = mbase + hf * 8;
                float v0 = acc[mt][nt][hf * 2 + 0] + b0;
                float v1 = acc[mt][nt][hf * 2 + 1] + b1;
                if (mat == 0) { v0 *= QSCALE; v1 *= QSCALE; }
                int b_ = mm >> 11, s = mm & (SEQ - 1);
                size_t bh = (size_t)(b_ * NH + hh);
                *(uint32_t*)(dst + (bh * SEQ + s) * DH + d) = packhf(v0, v1);
            }
        }
    }
}

// ---------------------------------------------------------------------------
// Flash attention: single-term fp16 HMMA, fixed softmax max, 3-stage
// cp.async ring over 64-key K/V tiles, mask preloaded in smem.
// CTA = 128 q-rows (8 warps x 16), 256 threads, 2 CTAs/SM.
// Dynamic smem: 3 stages x 2 arrays x 9216 B + 8192 B mask = 63488 B.
// ---------------------------------------------------------------------------
#define ARR_B   9216u
#define STAGE_B 18432u
#define MASK_OFF 55296u
#define NKT     (SEQ / 64)

__global__ __launch_bounds__(256, 2) void attn_mma_kernel(
    const float* __restrict__ mask, float* __restrict__ out)
{
    const int tid  = threadIdx.x;
    const int lane = tid & 31;
    const int wid  = tid >> 5;

    const int bh = blockIdx.y;
    const int b  = bh >> 4;
    const int h  = bh & 15;
    const int q0 = blockIdx.x * 128 + wid * 16;

    const uint32_t smBase = cvta_sm(dsm);
    float* smMask = (float*)(dsm + MASK_OFF);

    const int lrow = tid >> 2;            // 0..63
    const int lcb  = (tid & 3) * 16;      // halves

    // preload mask row scaled to log2 domain (8 KB, once per CTA)
    {
        const float* mrow = mask + (size_t)b * SEQ;
        for (int i = tid * 4; i < SEQ; i += 256 * 4) {
            float4 v = *(const float4*)(mrow + i);
            v.x *= LOG2E; v.y *= LOG2E; v.z *= LOG2E; v.w *= LOG2E;
            *(float4*)(smMask + i) = v;
        }
    }

    auto load_tile = [&](int stage, int k0) {
        size_t ko = ((size_t)bh * SEQ + k0 + lrow) * DH + lcb;
        uint32_t so = smBase + stage * STAGE_B + (uint32_t)(lrow * 72 + lcb) * 2;
        cp16(so,              g_k + ko);
        cp16(so + 16,         g_k + ko + 8);
        cp16(so + ARR_B,      g_v + ko);
        cp16(so + ARR_B + 16, g_v + ko + 8);
    };

    // Q fragments (fp16, prescaled to log2 domain)
    uint32_t qf[4][4];
    {
        const __half* qb = g_q + ((size_t)bh * SEQ + q0) * DH;
#pragma unroll
        for (int ks = 0; ks < 4; ks++)
            ldA_g16(qf[ks], qb, ks * 16, DH, lane);
    }

    float oacc[8][4];
#pragma unroll
    for (int j = 0; j < 8; j++)
#pragma unroll
        for (int u = 0; u < 4; u++) oacc[j][u] = 0.0f;
    float l1 = 0.0f, l2 = 0.0f;

    load_tile(0, 0);
    CP_COMMIT();
    load_tile(1, 64);
    CP_COMMIT();
    load_tile(2, 128);
    CP_COMMIT();

    for (int kt = 0; kt < NKT; kt++) {
        const int st = kt % 3;
        if (kt + 2 < NKT)      { CP_WAIT(2); }
        else if (kt + 1 < NKT) { CP_WAIT(1); }
        else                   { CP_WAIT(0); }
        __syncthreads();   // mask preload (kt=0) + all warps see stage st data

        const uint32_t aK = smBase + st * STAGE_B;
        const uint32_t aV = aK + ARR_B;
        const int k0 = kt * 64;

        // S = Q K^T
        float sacc[8][4];
#pragma unroll
        for (int j = 0; j < 8; j++)
#pragma unroll
            for (int u = 0; u < 4; u++) sacc[j][u] = 0.0f;
#pragma unroll
        for (int ks = 0; ks < 4; ks++) {
#pragma unroll
            for (int np = 0; np < 4; np++) {
                uint32_t bb[4];
                ldsm_x4(bb, addrB(aK, np * 16, ks * 16, 72, lane));
                mma_f16(sacc[2 * np],     qf[ks], bb);
                mma_f16(sacc[2 * np + 1], qf[ks], bb + 2);
            }
        }

        // p = 2^(s + mask_log2)  (mask from smem)
#pragma unroll
        for (int nt = 0; nt < 8; nt++) {
            float2 mk = *(const float2*)&smMask[k0 + nt * 8 + ((lane & 3) << 1)];
            sacc[nt][0] = ex2f(sacc[nt][0] + mk.x);
            sacc[nt][1] = ex2f(sacc[nt][1] + mk.y);
            sacc[nt][2] = ex2f(sacc[nt][2] + mk.x);
            sacc[nt][3] = ex2f(sacc[nt][3] + mk.y);
            l1 += sacc[nt][0] + sacc[nt][1];
            l2 += sacc[nt][2] + sacc[nt][3];
        }

        // O += P V (V^T via ldmatrix.trans)
#pragma unroll
        for (int t = 0; t < 4; t++) {
            uint32_t ah[4];
            ah[0] = packhf(sacc[2*t][0],   sacc[2*t][1]);
            ah[1] = packhf(sacc[2*t][2],   sacc[2*t][3]);
            ah[2] = packhf(sacc[2*t+1][0], sacc[2*t+1][1]);
            ah[3] = packhf(sacc[2*t+1][2], sacc[2*t+1][3]);
#pragma unroll
            for (int dp = 0; dp < 4; dp++) {
                uint32_t bv[4];
                ldsm_x4_t(bv, addrVT(aV, dp * 16, t * 16, 72, lane));
                mma_f16(oacc[2 * dp],     ah, bv);
                mma_f16(oacc[2 * dp + 1], ah, bv + 2);
            }
        }

        __syncthreads();   // all warps done with stage st before overwrite
        if (kt + 3 < NKT) {
            load_tile(st, (kt + 3) * 64);
            CP_COMMIT();
        }
    }

    // final row-sum reduction over the quad
#pragma unroll
    for (int off = 1; off < 4; off <<= 1) {
        l1 += __shfl_xor_sync(0xffffffffu, l1, off);
        l2 += __shfl_xor_sync(0xffffffffu, l2, off);
    }
    float inv1 = 1.0f / l1;
    float inv2 = 1.0f / l2;
    const int s1 = q0 + (lane >> 2);
    const int s2 = s1 + 8;
#pragma unroll
    for (int dt = 0; dt < 8; dt++) {
        int d = dt * 8 + ((lane & 3) << 1);
        float2 o1, o2;
        o1.x = oacc[dt][0] * inv1; o1.y = oacc[dt][1] * inv1;
        o2.x = oacc[dt][2] * inv2; o2.y = oacc[dt][3] * inv2;
        *(float2*)&out[((size_t)b * SEQ + s1) * HSZ + h * DH + d] = o1;
        *(float2*)&out[((size_t)b * SEQ + s2) * HSZ + h * DH + d] = o2;
    }
}

extern "C" void kernel_launch(void* const* d_in, const int* in_sizes, int n_in,
                              void* d_out, int out_size)
{
    const float* hidden = (const float*)d_in[0];
    const float* mask   = (const float*)d_in[1];
    const float* Wq     = (const float*)d_in[2];
    const float* bq     = (const float*)d_in[3];
    const float* Wk     = (const float*)d_in[4];
    const float* bk     = (const float*)d_in[5];
    const float* Wv     = (const float*)d_in[6];
    const float* bv     = (const float*)d_in[7];
    float* out = (float*)d_out;

    conv_x_kernel<<<(MTOT * HSZ) / (256 * 4), 256>>>(hidden);
    conv_w_kernel<<<dim3(HSZ / 32, HSZ / 32, 3), 256>>>(Wq, Wk, Wv);

    const int QKV_SMEM = 73728;
    cudaFuncSetAttribute(qkv_mma_kernel,
                         cudaFuncAttributeMaxDynamicSharedMemorySize, QKV_SMEM);
    qkv_mma_kernel<<<dim3(8, 32, 3), 256, QKV_SMEM>>>(bq, bk, bv);

    const int ATTN_SMEM = 63488;
    cudaFuncSetAttribute(attn_mma_kernel,
                         cudaFuncAttributeMaxDynamicSharedMemorySize, ATTN_SMEM);
    attn_mma_kernel<<<dim3(SEQ / 128, NB * NH), 256, ATTN_SMEM>>>(mask, out);
}

// round 17
// speedup vs baseline: 1.1116x; 1.0079x over previous
#include <cuda_runtime.h>
#include <cuda_fp16.h>
#include <math.h>
#include <stdint.h>

#define HSZ 1024
#define NH 16
#define DH 64
#define SEQ 2048
#define NB 2
#define MTOT (NB*SEQ)
#define LOG2E 1.4426950408889634f
#define QSCALE (0.125f * LOG2E)

// fp16 GEMM inputs
__device__ __half g_x[(size_t)MTOT * HSZ];
__device__ __half g_w[3 * (size_t)HSZ * HSZ];   // transposed [n][k]
// attention operands, single fp16, [bh][s][d]
__device__ __half g_q[(size_t)MTOT * HSZ];   // pre-scaled by 0.125*log2e
__device__ __half g_k[(size_t)MTOT * HSZ];
__device__ __half g_v[(size_t)MTOT * HSZ];

// ---------------------------------------------------------------------------
// mma / ldmatrix / cp.async helpers
// ---------------------------------------------------------------------------
__device__ __forceinline__ void mma_f16(float d[4], const uint32_t a[4],
                                        const uint32_t b[2]) {
    asm volatile(
        "mma.sync.aligned.m16n8k16.row.col.f32.f16.f16.f32 "
        "{%0,%1,%2,%3}, {%4,%5,%6,%7}, {%8,%9}, {%0,%1,%2,%3};\n"
        : "+f"(d[0]), "+f"(d[1]), "+f"(d[2]), "+f"(d[3])
        : "r"(a[0]), "r"(a[1]), "r"(a[2]), "r"(a[3]), "r"(b[0]), "r"(b[1]));
}
__device__ __forceinline__ uint32_t cvta_sm(const void* p) {
    uint32_t a;
    asm("{ .reg .u64 t; cvta.to.shared.u64 t, %1; cvt.u32.u64 %0, t; }"
        : "=r"(a) : "l"(p));
    return a;
}
__device__ __forceinline__ void ldsm_x4(uint32_t r[4], uint32_t addr) {
    asm volatile("ldmatrix.sync.aligned.m8n8.x4.shared.b16 {%0,%1,%2,%3}, [%4];"
                 : "=r"(r[0]), "=r"(r[1]), "=r"(r[2]), "=r"(r[3]) : "r"(addr));
}
__device__ __forceinline__ void ldsm_x4_t(uint32_t r[4], uint32_t addr) {
    asm volatile("ldmatrix.sync.aligned.m8n8.x4.trans.shared.b16 {%0,%1,%2,%3}, [%4];"
                 : "=r"(r[0]), "=r"(r[1]), "=r"(r[2]), "=r"(r[3]) : "r"(addr));
}
__device__ __forceinline__ void cp16(uint32_t dst, const void* src) {
    asm volatile("cp.async.cg.shared.global [%0], [%1], 16;"
                 :: "r"(dst), "l"(src) : "memory");
}
#define CP_COMMIT() asm volatile("cp.async.commit_group;" ::: "memory")
#define CP_WAIT(n)  asm volatile("cp.async.wait_group %0;" :: "n"(n) : "memory")

__device__ __forceinline__ uint32_t addrA(uint32_t base, int r0, int k0,
                                          int stride, int lane) {
    int row = r0 + (lane & 7) + ((lane >> 3) & 1) * 8;
    int col = k0 + (lane >> 4) * 8;
    return base + (uint32_t)(row * stride + col) * 2;
}
__device__ __forceinline__ uint32_t addrB(uint32_t base, int n0, int k0,
                                          int stride, int lane) {
    int row = n0 + (lane & 7) + (lane >> 4) * 8;
    int col = k0 + ((lane >> 3) & 1) * 8;
    return base + (uint32_t)(row * stride + col) * 2;
}
__device__ __forceinline__ uint32_t addrVT(uint32_t base, int d0, int s0,
                                           int stride, int lane) {
    int row = s0 + (lane & 7) + ((lane >> 3) & 1) * 8;
    int col = d0 + (lane >> 4) * 8;
    return base + (uint32_t)(row * stride + col) * 2;
}
__device__ __forceinline__ void ldA_g16(uint32_t a[4], const __half* base,
                                        int k0, int stride, int lane) {
    const __half* p = base + (size_t)(lane >> 2) * stride + k0 + ((lane & 3) << 1);
    a[0] = *(const uint32_t*)p;
    a[1] = *(const uint32_t*)(p + 8 * stride);
    a[2] = *(const uint32_t*)(p + 8);
    a[3] = *(const uint32_t*)(p + 8 * stride + 8);
}
__device__ __forceinline__ uint32_t packhf(float lo, float hi) {
    uint32_t r;
    asm("cvt.rn.f16x2.f32 %0, %1, %2;" : "=r"(r) : "f"(hi), "f"(lo));
    return r;
}
__device__ __forceinline__ uint32_t hadd2(uint32_t a, uint32_t b) {
    uint32_t r;
    asm("add.rn.f16x2 %0, %1, %2;" : "=r"(r) : "r"(a), "r"(b));
    return r;
}
__device__ __forceinline__ uint32_t h2exp2(uint32_t x) {
    uint32_t r;
    asm("ex2.approx.f16x2 %0, %1;" : "=r"(r) : "r"(x));
    return r;
}
__device__ __forceinline__ float2 h2_to_f2(uint32_t h) {
    __half2 v = *(__half2*)&h;
    return make_float2(__half2float(v.x), __half2float(v.y));
}

// ---------------------------------------------------------------------------
// Convert hidden_states to fp16
// ---------------------------------------------------------------------------
__global__ __launch_bounds__(256) void conv_x_kernel(const float* __restrict__ X)
{
    size_t i = ((size_t)blockIdx.x * 256 + threadIdx.x) * 4;
    float4 v = *(const float4*)(X + i);
    uint32_t p0 = packhf(v.x, v.y);
    uint32_t p1 = packhf(v.z, v.w);
    *(uint32_t*)(g_x + i)     = p0;
    *(uint32_t*)(g_x + i + 2) = p1;
}

// ---------------------------------------------------------------------------
// Transpose + convert weights: Wt[n][k] = W[k][n], fp16
// ---------------------------------------------------------------------------
__global__ __launch_bounds__(256) void conv_w_kernel(
    const float* __restrict__ Wq, const float* __restrict__ Wk,
    const float* __restrict__ Wv)
{
    __shared__ float t[32][33];
    const int z = blockIdx.z;
    const float* W = (z == 0) ? Wq : (z == 1) ? Wk : Wv;
    __half* T = g_w + (size_t)z * HSZ * HSZ;

    const int n0 = blockIdx.x * 32;
    const int k0 = blockIdx.y * 32;
    const int tx = threadIdx.x & 31;
    const int ty = threadIdx.x >> 5;

#pragma unroll
    for (int j = 0; j < 4; j++) {
        int k = k0 + ty + j * 8;
        t[ty + j * 8][tx] = W[(size_t)k * HSZ + n0 + tx];
    }
    __syncthreads();
#pragma unroll
    for (int j = 0; j < 4; j++) {
        int r = ty + j * 8;
        T[(size_t)(n0 + r) * HSZ + k0 + tx] = __float2half(t[tx][r]);
    }
}

// ---------------------------------------------------------------------------
// QKV GEMM, single-term fp16 HMMA, ldmatrix + cp.async double buffer.
// CTA 128x128, BK=64, 8 warps, 2 CTAs/SM.
// Dynamic smem: 2 stages x 2 arrays x 18432 B = 73728 B.
// ---------------------------------------------------------------------------
extern __shared__ __align__(16) char dsm[];

#define QARR_B   18432u
#define QSTAGE_B 36864u

__global__ __launch_bounds__(256, 2) void qkv_mma_kernel(
    const float* __restrict__ bq, const float* __restrict__ bk,
    const float* __restrict__ bv)
{
    const int tid  = threadIdx.x;
    const int lane = tid & 31;
    const int wid  = tid >> 5;
    const int wr   = wid >> 1;
    const int wc   = wid & 1;

    const int n0  = blockIdx.x * 128;
    const int m0  = blockIdx.y * 128;
    const int mat = blockIdx.z;

    const __half* Wt = g_w + (size_t)mat * HSZ * HSZ;
    const float* bias = (mat == 0) ? bq : (mat == 1) ? bk : bv;

    const uint32_t smBase = cvta_sm(dsm);

    const int lrow = tid >> 1;            // 0..127
    const int lcb  = (tid & 1) * 32;      // halves

    auto load_chunk = [&](int st, int gk) {
        size_t ga = (size_t)(m0 + lrow) * HSZ + gk + lcb;
        size_t gb = (size_t)(n0 + lrow) * HSZ + gk + lcb;
        uint32_t so = smBase + st * QSTAGE_B + (uint32_t)(lrow * 72 + lcb) * 2;
#pragma unroll
        for (int u = 0; u < 4; u++) {
            cp16(so + u * 16,          g_x + ga + u * 8);
            cp16(so + QARR_B + u * 16, Wt + gb + u * 8);
        }
    };

    float acc[2][8][4];
#pragma unroll
    for (int i = 0; i < 2; i++)
#pragma unroll
        for (int j = 0; j < 8; j++)
#pragma unroll
            for (int u = 0; u < 4; u++) acc[i][j][u] = 0.0f;

    load_chunk(0, 0);
    CP_COMMIT();
    load_chunk(1, 64);
    CP_COMMIT();

    const int NCH = HSZ / 64;   // 16
    for (int kc = 0; kc < NCH; kc++) {
        const int st = kc & 1;
        if (kc + 1 < NCH) { CP_WAIT(1); } else { CP_WAIT(0); }
        __syncthreads();

        const uint32_t bA = smBase + st * QSTAGE_B;
        const uint32_t bB = bA + QARR_B;

#pragma unroll
        for (int ks = 0; ks < 4; ks++) {
            uint32_t a0[4], a1[4];
            ldsm_x4(a0, addrA(bA, wr * 32,      ks * 16, 72, lane));
            ldsm_x4(a1, addrA(bA, wr * 32 + 16, ks * 16, 72, lane));
#pragma unroll
            for (int np = 0; np < 4; np++) {
                uint32_t bb[4];
                ldsm_x4(bb, addrB(bB, wc * 64 + np * 16, ks * 16, 72, lane));
                mma_f16(acc[0][2 * np],     a0, bb);
                mma_f16(acc[0][2 * np + 1], a0, bb + 2);
                mma_f16(acc[1][2 * np],     a1, bb);
                mma_f16(acc[1][2 * np + 1], a1, bb + 2);
            }
        }

        __syncthreads();
        if (kc + 2 < NCH) {
            load_chunk(st, (kc + 2) * 64);
            CP_COMMIT();
        }
    }

    // epilogue: bias, (Q prescale), pack fp16, store [bh][s][d]
    __half* dst = (mat == 0) ? g_q : (mat == 1) ? g_k : g_v;
#pragma unroll
    for (int mt = 0; mt < 2; mt++) {
#pragma unroll
        for (int nt = 0; nt < 8; nt++) {
            int mbase = m0 + wr * 32 + mt * 16 + (lane >> 2);
            int c = n0 + wc * 64 + nt * 8 + ((lane & 3) << 1);
            float b0 = bias[c], b1 = bias[c + 1];
            int hh = c >> 6, d = c & 63;
#pragma unroll
            for (int hf = 0; hf < 2; hf++) {
                int mm = mbase + hf * 8;
                float v0 = acc[mt][nt][hf * 2 + 0] + b0;
                float v1 = acc[mt][nt][hf * 2 + 1] + b1;
                if (mat == 0) { v0 *= QSCALE; v1 *= QSCALE; }
                int b_ = mm >> 11, s = mm & (SEQ - 1);
                size_t bh = (size_t)(b_ * NH + hh);
                *(uint32_t*)(dst + (bh * SEQ + s) * DH + d) = packhf(v0, v1);
            }
        }
    }
}

// ---------------------------------------------------------------------------
// Flash attention: single-term fp16 HMMA, fixed softmax max, 3-stage
// cp.async ring, f16x2 vectorized softmax (ex2.approx.f16x2), mask in smem
// as f16x2 (log2-scaled). CTA = 128 q-rows (8 warps), 256 threads, 2 CTAs/SM.
// Dynamic smem: 3 stages x 2 arrays x 9216 B + 4096 B mask = 59392 B.
// ---------------------------------------------------------------------------
#define ARR_B   9216u
#define STAGE_B 18432u
#define MASK_OFF 55296u
#define NKT     (SEQ / 64)

__global__ __launch_bounds__(256, 2) void attn_mma_kernel(
    const float* __restrict__ mask, float* __restrict__ out)
{
    const int tid  = threadIdx.x;
    const int lane = tid & 31;
    const int wid  = tid >> 5;

    const int bh = blockIdx.y;
    const int b  = bh >> 4;
    const int h  = bh & 15;
    const int q0 = blockIdx.x * 128 + wid * 16;

    const uint32_t smBase = cvta_sm(dsm);
    __half* smMask = (__half*)(dsm + MASK_OFF);

    const int lrow = tid >> 2;            // 0..63
    const int lcb  = (tid & 3) * 16;      // halves

    // preload mask row: scale to log2 domain, convert to f16 (4 KB)
    {
        const float* mrow = mask + (size_t)b * SEQ;
        for (int i = tid * 4; i < SEQ; i += 256 * 4) {
            float4 v = *(const float4*)(mrow + i);
            uint32_t p0 = packhf(v.x * LOG2E, v.y * LOG2E);
            uint32_t p1 = packhf(v.z * LOG2E, v.w * LOG2E);
            *(uint32_t*)(smMask + i)     = p0;
            *(uint32_t*)(smMask + i + 2) = p1;
        }
    }

    auto load_tile = [&](int stage, int k0) {
        size_t ko = ((size_t)bh * SEQ + k0 + lrow) * DH + lcb;
        uint32_t so = smBase + stage * STAGE_B + (uint32_t)(lrow * 72 + lcb) * 2;
        cp16(so,              g_k + ko);
        cp16(so + 16,         g_k + ko + 8);
        cp16(so + ARR_B,      g_v + ko);
        cp16(so + ARR_B + 16, g_v + ko + 8);
    };

    // Q fragments (fp16, prescaled to log2 domain)
    uint32_t qf[4][4];
    {
        const __half* qb = g_q + ((size_t)bh * SEQ + q0) * DH;
#pragma unroll
        for (int ks = 0; ks < 4; ks++)
            ldA_g16(qf[ks], qb, ks * 16, DH, lane);
    }

    float oacc[8][4];
#pragma unroll
    for (int j = 0; j < 8; j++)
#pragma unroll
        for (int u = 0; u < 4; u++) oacc[j][u] = 0.0f;
    float l1 = 0.0f, l2 = 0.0f;

    load_tile(0, 0);
    CP_COMMIT();
    load_tile(1, 64);
    CP_COMMIT();
    load_tile(2, 128);
    CP_COMMIT();

    for (int kt = 0; kt < NKT; kt++) {
        const int st = kt % 3;
        if (kt + 2 < NKT)      { CP_WAIT(2); }
        else if (kt + 1 < NKT) { CP_WAIT(1); }
        else                   { CP_WAIT(0); }
        __syncthreads();

        const uint32_t aK = smBase + st * STAGE_B;
        const uint32_t aV = aK + ARR_B;
        const int k0 = kt * 64;

        // S = Q K^T
        float sacc[8][4];
#pragma unroll
        for (int j = 0; j < 8; j++)
#pragma unroll
            for (int u = 0; u < 4; u++) sacc[j][u] = 0.0f;
#pragma unroll
        for (int ks = 0; ks < 4; ks++) {
#pragma unroll
            for (int np = 0; np < 4; np++) {
                uint32_t bb[4];
                ldsm_x4(bb, addrB(aK, np * 16, ks * 16, 72, lane));
                mma_f16(sacc[2 * np],     qf[ks], bb);
                mma_f16(sacc[2 * np + 1], qf[ks], bb + 2);
            }
        }

        // p = 2^(s + mask_log2) in f16x2; results feed PV A-fragments directly
        uint32_t p01[8], p23[8];
        uint32_t sum01 = 0, sum23 = 0;   // f16x2 per-tile partial row sums
#pragma unroll
        for (int nt = 0; nt < 8; nt++) {
            uint32_t mk = *(uint32_t*)&smMask[k0 + nt * 8 + ((lane & 3) << 1)];
            uint32_t h01 = hadd2(packhf(sacc[nt][0], sacc[nt][1]), mk);
            uint32_t h23 = hadd2(packhf(sacc[nt][2], sacc[nt][3]), mk);
            p01[nt] = h2exp2(h01);
            p23[nt] = h2exp2(h23);
            sum01 = hadd2(sum01, p01[nt]);
            sum23 = hadd2(sum23, p23[nt]);
        }
        {
            float2 s1f = h2_to_f2(sum01);
            float2 s2f = h2_to_f2(sum23);
            l1 += s1f.x + s1f.y;
            l2 += s2f.x + s2f.y;
        }

        // O += P V (V^T via ldmatrix.trans); A-fragments are p01/p23
#pragma unroll
        for (int t = 0; t < 4; t++) {
            uint32_t ah[4];
            ah[0] = p01[2 * t];
            ah[1] = p23[2 * t];
            ah[2] = p01[2 * t + 1];
            ah[3] = p23[2 * t + 1];
#pragma unroll
            for (int dp = 0; dp < 4; dp++) {
                uint32_t bv[4];
                ldsm_x4_t(bv, addrVT(aV, dp * 16, t * 16, 72, lane));
                mma_f16(oacc[2 * dp],     ah, bv);
                mma_f16(oacc[2 * dp + 1], ah, bv + 2);
            }
        }

        __syncthreads();
        if (kt + 3 < NKT) {
            load_tile(st, (kt + 3) * 64);
            CP_COMMIT();
        }
    }

    // final row-sum reduction over the quad
#pragma unroll
    for (int off = 1; off < 4; off <<= 1) {
        l1 += __shfl_xor_sync(0xffffffffu, l1, off);
        l2 += __shfl_xor_sync(0xffffffffu, l2, off);
    }
    float inv1 = 1.0f / l1;
    float inv2 = 1.0f / l2;
    const int s1 = q0 + (lane >> 2);
    const int s2 = s1 + 8;
#pragma unroll
    for (int dt = 0; dt < 8; dt++) {
        int d = dt * 8 + ((lane & 3) << 1);
        float2 o1, o2;
        o1.x = oacc[dt][0] * inv1; o1.y = oacc[dt][1] * inv1;
        o2.x = oacc[dt][2] * inv2; o2.y = oacc[dt][3] * inv2;
        *(float2*)&out[((size_t)b * SEQ + s1) * HSZ + h * DH + d] = o1;
        *(float2*)&out[((size_t)b * SEQ + s2) * HSZ + h * DH + d] = o2;
    }
}

extern "C" void kernel_launch(void* const* d_in, const int* in_sizes, int n_in,
                              void* d_out, int out_size)
{
    const float* hidden = (const float*)d_in[0];
    const float* mask   = (const float*)d_in[1];
    const float* Wq     = (const float*)d_in[2];
    const float* bq     = (const float*)d_in[3];
    const float* Wk     = (const float*)d_in[4];
    const float* bk     = (const float*)d_in[5];
    const float* Wv     = (const float*)d_in[6];
    const float* bv     = (const float*)d_in[7];
    float* out = (float*)d_out;

    conv_x_kernel<<<(MTOT * HSZ) / (256 * 4), 256>>>(hidden);
    conv_w_kernel<<<dim3(HSZ / 32, HSZ / 32, 3), 256>>>(Wq, Wk, Wv);

    const int QKV_SMEM = 73728;
    cudaFuncSetAttribute(qkv_mma_kernel,
                         cudaFuncAttributeMaxDynamicSharedMemorySize, QKV_SMEM);
    qkv_mma_kernel<<<dim3(8, 32, 3), 256, QKV_SMEM>>>(bq, bk, bv);

    const int ATTN_SMEM = 59392;
    cudaFuncSetAttribute(attn_mma_kernel,
                         cudaFuncAttributeMaxDynamicSharedMemorySize, ATTN_SMEM);
    attn_mma_kernel<<<dim3(SEQ / 128, NB * NH), 256, ATTN_SMEM>>>(mask, out);
}